// round 17
// baseline (speedup 1.0000x reference)
#include <cuda_runtime.h>
#include <cstddef>

#define NJ 24

__device__ float g_partials[16384];
__device__ unsigned int g_count = 0;

// Fast inverse sqrt on the FMA pipe (avoids MUFU throughput bound).
__device__ __forceinline__ float rsq(float x) {
    float y = __int_as_float(0x5f3759dfu - (__float_as_uint(x) >> 1));
    float hx = 0.5f * x;
    y = y * (1.5f - hx * y * y);
    y = y * (1.5f - hx * y * y);
    return y;
}

// 256-bit global load (Blackwell LDG.E.256). p must be 32B-aligned.
__device__ __forceinline__ void ldg256(const float* __restrict__ p, float* w) {
    asm("ld.global.v8.f32 {%0,%1,%2,%3,%4,%5,%6,%7}, [%8];"
        : "=f"(w[0]), "=f"(w[1]), "=f"(w[2]), "=f"(w[3]),
          "=f"(w[4]), "=f"(w[5]), "=f"(w[6]), "=f"(w[7])
        : "l"(p));
}

// Forward kinematics for one frame of ONE pose; emits the 5 end-site positions.
// poseF: 144 floats (24 x 6) = 18 x 32B chunks; offF: 72 floats = 9 x 32B.
// All loads are LDG.256 (halved L1tex wavefront count vs LDG.128).
__device__ __forceinline__ void fk_ee(const float* __restrict__ poseF,
                                      const float* __restrict__ offF,
                                      float ee[5][3])
{
    constexpr int PARENTS[NJ] = {-1,0,0,0,1,2,3,4,5,6,7,8,9,9,9,12,13,14,16,17,18,19,20,21};
    constexpr bool IS_EE[NJ] = {false,false,false,false,false,false,false,false,false,false,
                                true, true, false,false,false,true, false,false,false,false,
                                false,false,true, true};
    constexpr int EE_SLOT[NJ] = {-1,-1,-1,-1,-1,-1,-1,-1,-1,-1,
                                  0, 1,-1,-1,-1, 2,-1,-1,-1,-1,
                                 -1,-1, 3, 4};

    float O[NJ][9];   // global orientations (row-major); scalarized by full unroll
    float P[NJ][3];   // global positions
    float pw[24];     // pose window: 4 joints (24 floats = 3 x v8)
    float ow[24];     // offset window: 8 joints (24 floats = 3 x v8)

#pragma unroll
    for (int i = 0; i < NJ; ++i) {
        if ((i & 3) == 0) {           // refill pose window: floats 6i..6i+23
            ldg256(poseF + 6 * i,      pw);
            ldg256(poseF + 6 * i + 8,  pw + 8);
            ldg256(poseF + 6 * i + 16, pw + 16);
        }
        const int m = 6 * (i & 3);
        const float a0 = pw[m],     a1 = pw[m + 1], a2 = pw[m + 2];
        const float a3 = pw[m + 3], a4 = pw[m + 4], a5 = pw[m + 5];

        if ((i & 7) == 0) {           // refill offset window: floats 3i..3i+23
            ldg256(offF + 3 * i,      ow);
            ldg256(offF + 3 * i + 8,  ow + 8);
            ldg256(offF + 3 * i + 16, ow + 16);
        }
        const int t = 3 * (i & 7);
        const float ox = ow[t], oy = ow[t + 1], oz = ow[t + 2];

        // 6D -> rotation matrix (rows b1,b2,b3). Skipped for leaf end-sites.
        float r0 = 0.f, r1 = 0.f, r2 = 0.f, r3 = 0.f, r4 = 0.f,
              r5 = 0.f, r6 = 0.f, r7 = 0.f, r8 = 0.f;
        if (!IS_EE[i]) {
            const float n1 = a0 * a0 + a1 * a1 + a2 * a2;
            const float i1 = rsq(n1);
            r0 = a0 * i1; r1 = a1 * i1; r2 = a2 * i1;
            const float d  = r0 * a3 + r1 * a4 + r2 * a5;
            const float c0 = a3 - d * r0;
            const float c1 = a4 - d * r1;
            const float c2 = a5 - d * r2;
            const float n2 = c0 * c0 + c1 * c1 + c2 * c2;
            const float i2 = rsq(n2);
            r3 = c0 * i2; r4 = c1 * i2; r5 = c2 * i2;
            r6 = r1 * r5 - r2 * r4;
            r7 = r2 * r3 - r0 * r5;
            r8 = r0 * r4 - r1 * r3;
        }

        if (i == 0) {
            P[0][0] = ox; P[0][1] = oy; P[0][2] = oz;
            O[0][0] = r0; O[0][1] = r1; O[0][2] = r2;
            O[0][3] = r3; O[0][4] = r4; O[0][5] = r5;
            O[0][6] = r6; O[0][7] = r7; O[0][8] = r8;
        } else {
            const int p = PARENTS[i];
            const float px = O[p][0] * ox + O[p][1] * oy + O[p][2] * oz + P[p][0];
            const float py = O[p][3] * ox + O[p][4] * oy + O[p][5] * oz + P[p][1];
            const float pz = O[p][6] * ox + O[p][7] * oy + O[p][8] * oz + P[p][2];
            if (IS_EE[i]) {
                const int s = EE_SLOT[i];
                ee[s][0] = px; ee[s][1] = py; ee[s][2] = pz;
            } else {
                P[i][0] = px; P[i][1] = py; P[i][2] = pz;
                // O[i] = O[p] @ R
                O[i][0] = O[p][0] * r0 + O[p][1] * r3 + O[p][2] * r6;
                O[i][1] = O[p][0] * r1 + O[p][1] * r4 + O[p][2] * r7;
                O[i][2] = O[p][0] * r2 + O[p][1] * r5 + O[p][2] * r8;
                O[i][3] = O[p][3] * r0 + O[p][4] * r3 + O[p][5] * r6;
                O[i][4] = O[p][3] * r1 + O[p][4] * r4 + O[p][5] * r7;
                O[i][5] = O[p][3] * r2 + O[p][4] * r5 + O[p][5] * r8;
                O[i][6] = O[p][6] * r0 + O[p][7] * r3 + O[p][8] * r6;
                O[i][7] = O[p][6] * r1 + O[p][7] * r4 + O[p][8] * r7;
                O[i][8] = O[p][6] * r2 + O[p][7] * r5 + O[p][8] * r8;
            }
        }
    }
}

// LANE-PAIR split: even lane = pose A, odd lane = pose B of the same frame.
// Scaled EE values are exchanged via shfl_xor(1); both lanes accumulate the
// identical square -> final scale includes an extra 1/2.
__global__ void __launch_bounds__(128, 6)
ee_loss_kernel(const float* __restrict__ poseA, const float* __restrict__ poseB,
               const float* __restrict__ offA,  const float* __restrict__ offB,
               const float* __restrict__ tA,    const float* __restrict__ tB,
               float* __restrict__ out,
               int F, int nb, float inv_count)
{
    constexpr int END_SITES[5] = {10,11,15,22,23};
    __shared__ float s_iS[2][3];
    __shared__ float s_c[2][15];     // c[p] = tP[ee] * iS[p]
    __shared__ float s_wsum[4];
    __shared__ bool  s_last;
    __shared__ double s_dsum[128];

    if (threadIdx.x == 0) {
        float mnA[3], mxA[3], mnB[3], mxB[3];
#pragma unroll
        for (int a = 0; a < 3; ++a) {
            mnA[a] = mxA[a] = tA[a];
            mnB[a] = mxB[a] = tB[a];
        }
#pragma unroll
        for (int j = 1; j < NJ; ++j) {
#pragma unroll
            for (int a = 0; a < 3; ++a) {
                const float va = tA[j * 3 + a];
                const float vb = tB[j * 3 + a];
                mnA[a] = fminf(mnA[a], va); mxA[a] = fmaxf(mxA[a], va);
                mnB[a] = fminf(mnB[a], vb); mxB[a] = fmaxf(mxB[a], vb);
            }
        }
#pragma unroll
        for (int a = 0; a < 3; ++a) {
            s_iS[0][a] = 1.0f / (mxA[a] - mnA[a]);
            s_iS[1][a] = 1.0f / (mxB[a] - mnB[a]);
        }
#pragma unroll
        for (int e = 0; e < 5; ++e) {
#pragma unroll
            for (int a = 0; a < 3; ++a) {
                s_c[0][e * 3 + a] = tA[END_SITES[e] * 3 + a] * s_iS[0][a];
                s_c[1][e * 3 + a] = tB[END_SITES[e] * 3 + a] * s_iS[1][a];
            }
        }
    }
    __syncthreads();

    const int gid   = blockIdx.x * blockDim.x + threadIdx.x;
    const int frame = gid >> 1;
    const int pb    = gid & 1;
    const bool valid = (frame < F);
    const int fr    = valid ? frame : (F - 1);    // clamp loads, guard accumulate

    float s = 0.0f;
    {
        const float* __restrict__ pose = pb ? poseB : poseA;
        const float* __restrict__ off  = pb ? offB  : offA;
        float ee[5][3];
        fk_ee(pose + (size_t)fr * 144, off + (size_t)fr * 72, ee);

        const float i0 = s_iS[pb][0], i1 = s_iS[pb][1], i2 = s_iS[pb][2];
#pragma unroll
        for (int e = 0; e < 5; ++e) {
            const float v0 = ee[e][0] * i0 - s_c[pb][e * 3 + 0];
            const float v1 = ee[e][1] * i1 - s_c[pb][e * 3 + 1];
            const float v2 = ee[e][2] * i2 - s_c[pb][e * 3 + 2];
            const float w0 = __shfl_xor_sync(0xFFFFFFFFu, v0, 1);
            const float w1 = __shfl_xor_sync(0xFFFFFFFFu, v1, 1);
            const float w2 = __shfl_xor_sync(0xFFFFFFFFu, v2, 1);
            if (valid) {
                const float d0 = v0 - w0, d1 = v1 - w1, d2 = v2 - w2;
                s = fmaf(d0, d0, s);
                s = fmaf(d1, d1, s);
                s = fmaf(d2, d2, s);
            }
        }
    }

    // deterministic in-block reduction
#pragma unroll
    for (int o = 16; o > 0; o >>= 1)
        s += __shfl_xor_sync(0xFFFFFFFFu, s, o);
    const int wid  = threadIdx.x >> 5;
    const int lane = threadIdx.x & 31;
    if (lane == 0) s_wsum[wid] = s;
    __syncthreads();

    if (threadIdx.x == 0) {
        g_partials[blockIdx.x] = s_wsum[0] + s_wsum[1] + s_wsum[2] + s_wsum[3];
        __threadfence();
        const unsigned int done = atomicAdd(&g_count, 1u);
        s_last = (done == (unsigned int)(nb - 1));
    }
    __syncthreads();

    // Last block to finish reduces all partials in a FIXED order
    // (independent of which block it is) -> deterministic; writes d_out
    // directly so the graph has a single kernel node.
    if (s_last) {
        double ds = 0.0;
        for (int i = threadIdx.x; i < nb; i += 128)
            ds += (double)g_partials[i];
        s_dsum[threadIdx.x] = ds;
        __syncthreads();
#pragma unroll
        for (int k = 64; k > 0; k >>= 1) {
            if (threadIdx.x < k) s_dsum[threadIdx.x] += s_dsum[threadIdx.x + k];
            __syncthreads();
        }
        if (threadIdx.x == 0) {
            out[0] = (float)(s_dsum[0] * (double)inv_count);
            g_count = 0;   // reset for the next graph replay
        }
    }
}

extern "C" void kernel_launch(void* const* d_in, const int* in_sizes, int n_in,
                              void* d_out, int out_size)
{
    const float* poseA = (const float*)d_in[0];
    const float* poseB = (const float*)d_in[1];
    const float* offA  = (const float*)d_in[2];
    const float* offB  = (const float*)d_in[3];
    const float* tA    = (const float*)d_in[4];
    const float* tB    = (const float*)d_in[5];
    float* out = (float*)d_out;

    const int F = in_sizes[0] / (NJ * 6);
    const int threads = 128;
    const int total = 2 * F;                    // one thread per (frame, pose)
    const int nb = (total + threads - 1) / threads;
    // Each pair's squared diff is accumulated by BOTH lanes -> extra /2.
    const float inv_count = 1.0f / ((float)F * 15.0f * 2.0f);

    ee_loss_kernel<<<nb, threads>>>(poseA, poseB, offA, offB, tA, tB, out, F, nb, inv_count);
}